// round 12
// baseline (speedup 1.0000x reference)
#include <cuda_runtime.h>
#include <cstdint>

// ---------------- problem constants ----------------
#define Hc    128
#define H1c   129
#define NROW  (H1c*H1c)         // 16641 (i,j) rows, each 129 k long
#define Bq    64
#define N1    64
#define N2    32
#define NCTA  152               // 1 CTA per SM
#define NTHR  512               // 16 warps
#define RPC   110               // rows per CTA (151*110=16610; last CTA 31)

// smem layout (floats)
#define ST_STRIDE 140           // sT row stride (conflict-free A frag LDS)
#define SB_STRIDE 72            // sB k-row stride (conflict-free B frag LDS)
#define SM_T      0                         // sT : 64 x 140          = 8960
#define SM_PM     8960                      // sPM: 110 x 64          = 7040
#define SM_SB     16000                     // sB : 3 x 129*72        = 27864
#define SB_FPB    (H1c*SB_STRIDE)           // 9288 floats / buf
#define SM_MBAR   (SM_SB + 3*SB_FPB)        // 43864 (8B aligned x4)
#define SM_FLOATS (SM_MBAR + 12)            // 43876 -> 175504 bytes

#define R_BYTES   (H1c * N1 * 4)            // 33024 B per r
#define SB_BYTES  (SB_FPB * 4)              // 37152 B per buf

__device__ float g_partial[NCTA * Bq * N1];
__device__ float g_Y1[Bq * N1];

// ---------------- helpers ----------------
__device__ __forceinline__ uint32_t smem_u32(const void* p) {
    uint32_t a;
    asm("{ .reg .u64 t; cvta.to.shared.u64 t, %1; cvt.u32.u64 %0, t; }" : "=r"(a) : "l"(p));
    return a;
}
__device__ __forceinline__ uint32_t elect1() {
    uint32_t p;
    asm volatile("{ .reg .pred p; elect.sync _|p, 0xFFFFFFFF; selp.b32 %0,1,0,p; }" : "=r"(p));
    return p;
}
__device__ __forceinline__ uint32_t to_tf32(float f) {
    uint32_t u;
    asm("cvt.rna.tf32.f32 %0, %1;" : "=r"(u) : "f"(f));
    return u;
}
__device__ __forceinline__ void mbar_init(uint32_t a, uint32_t cnt) {
    asm volatile("mbarrier.init.shared.b64 [%0], %1;" :: "r"(a), "r"(cnt) : "memory");
}
__device__ __forceinline__ void mbar_expect_tx(uint32_t a, uint32_t bytes) {
    asm volatile("mbarrier.arrive.expect_tx.shared.b64 _, [%0], %1;"
                 :: "r"(a), "r"(bytes) : "memory");
}
__device__ __forceinline__ void mbar_arrive(uint32_t a) {
    asm volatile("mbarrier.arrive.shared.b64 _, [%0];" :: "r"(a) : "memory");
}
__device__ __forceinline__ void bulk_g2s(uint32_t dst, const void* src,
                                         uint32_t bytes, uint32_t mbar) {
    asm volatile(
        "cp.async.bulk.shared::cluster.global.mbarrier::complete_tx::bytes "
        "[%0], [%1], %2, [%3];"
        :: "r"(dst), "l"(src), "r"(bytes), "r"(mbar) : "memory");
}
__device__ __forceinline__ void mbar_wait(uint32_t a, uint32_t par) {
    uint32_t done;
    asm volatile("{\n\t.reg .pred p;\n\t"
                 "mbarrier.try_wait.parity.acquire.cta.shared::cta.b64 p, [%1], %2;\n\t"
                 "selp.b32 %0,1,0,p;\n\t}" : "=r"(done) : "r"(a), "r"(par) : "memory");
    if (!done) {
        asm volatile("{\n\t.reg .pred P1;\n\tW%=:\n\t"
                     "mbarrier.try_wait.parity.acquire.cta.shared::cta.b64 P1, [%0], %1, 0x989680;\n\t"
                     "@P1 bra.uni D%=;\n\tbra.uni W%=;\n\tD%=:\n\t}"
                     :: "r"(a), "r"(par) : "memory");
    }
}
// D(16x8,f32) += A(16x8,tf32) * B(8x8,tf32)   row.col
__device__ __forceinline__ void mma_tf32(float* d, const uint32_t* a,
                                         uint32_t b0, uint32_t b1) {
    asm volatile(
        "mma.sync.aligned.m16n8k8.row.col.f32.tf32.tf32.f32 "
        "{%0,%1,%2,%3}, {%4,%5,%6,%7}, {%8,%9}, {%0,%1,%2,%3};"
        : "+f"(d[0]), "+f"(d[1]), "+f"(d[2]), "+f"(d[3])
        : "r"(a[0]), "r"(a[1]), "r"(a[2]), "r"(a[3]), "r"(b0), "r"(b1));
}

// ============================================================
// Kernel 1: factored GEMM, mbarrier-ring pipelined.
//   per r:  G = T_h[64x129] @ W1_r[129x64]  (16 tf32 ks + fp32 rank-1)
//           D += pm[r,:] (x) G              (fp32 epilogue)
// W1_r arrives as 129 x 256B cp.async.bulk rows DIRECTLY into the
// stride-72 MMA layout (no repack). 3-buffer full/empty mbarrier ring,
// zero __syncthreads in the mainloop; warp 0 is the producer.
// ============================================================
__global__ void __launch_bounds__(NTHR, 1)
k_main(const float* __restrict__ v, const float* __restrict__ a,
       const float* __restrict__ t, const float* __restrict__ W1)
{
    extern __shared__ float sm[];
    float* sT  = sm + SM_T;                 // [b*140 + c], c=0..128
    float* sPM = sm + SM_PM;                // [rloc*64 + b]
    const uint32_t base = smem_u32(sm);
    const uint32_t sb_u = base + SM_SB * 4;
    const uint32_t mbar = base + SM_MBAR * 4;
    #define FULLB(b)  (mbar + (b) * 8)
    #define EMPTYB(b) (mbar + 24 + (b) * 8)

    const int tid  = threadIdx.x;
    const int wid  = tid >> 5;
    const int lane = tid & 31;
    const int cta  = blockIdx.x;

    const int r0    = cta * RPC;
    const int nrows = (r0 < NROW) ? min(RPC, NROW - r0) : 0;
    if (nrows <= 0) {
        float* out = &g_partial[cta * (Bq * N1)];
        for (int i = tid; i < Bq * N1; i += NTHR) out[i] = 0.f;
        return;
    }
    const int i0 = r0 / H1c;
    const int i1 = (r0 + nrows - 1) / H1c;   // i spans at most {i0, i1}

    // --- staging (in sB region, dead before first bulk): vT + a columns ---
    float* vT = sm + SM_SB;                  // [c*65 + b], 8320 floats
    float* a2 = sm + SM_SB + 8320;           // [sel*64 + b]
    for (int idx = tid; idx < Bq * Hc; idx += NTHR) {
        int b = idx >> 7, c = idx & 127;
        vT[c * 65 + b] = v[idx];
    }
    if (tid < 128) {
        int c = tid >> 6, b = tid & 63;
        int ii = c ? i1 : i0;
        a2[c * 64 + b] = (ii == 0) ? 1.f : __ldg(&a[b * Hc + ii - 1]);
    }
    __syncthreads();

    // --- build pm slice (fp32) ---
    for (int idx = tid; idx < nrows * Bq; idx += NTHR) {
        int rloc = idx >> 6, b = idx & 63;
        int rg = r0 + rloc;
        int i  = rg / H1c;
        int j  = rg - i * H1c;
        float av = (i == i0) ? a2[b] : a2[64 + b];
        float vv = (j == 0) ? 1.f : vT[(j - 1) * 65 + b];
        sPM[idx] = av * vv;
    }
    // --- build sT: tf32-rounded for c<128, raw fp32 at c==128 ---
    for (int idx = tid; idx < Bq * H1c; idx += NTHR) {
        int b = idx / H1c;
        int c = idx - b * H1c;
        float val = (c == 0) ? 1.f : __ldg(&t[b * Hc + c - 1]);
        sT[b * ST_STRIDE + c] = (c < 128) ? __uint_as_float(to_tf32(val)) : val;
    }
    if (tid == 0) {
        #pragma unroll
        for (int b = 0; b < 3; b++) { mbar_init(FULLB(b), 1); mbar_init(EMPTYB(b), 16); }
    }
    __syncthreads();   // staging dead, mbars live

    // --- prologue: warp 0 fills up to 3 buffers ---
    if (wid == 0) {
        const int npro = (nrows < 3) ? nrows : 3;
        for (int pb = 0; pb < npro; pb++) {
            if (elect1()) mbar_expect_tx(FULLB(pb), R_BYTES);
            for (int row = lane; row < H1c; row += 32)
                bulk_g2s(sb_u + pb * SB_BYTES + row * (SB_STRIDE * 4),
                         W1 + ((long long)(r0 + pb) * H1c + row) * N1,
                         N1 * 4, FULLB(pb));
        }
    }

    // --- warp geometry: 16 warps = 4 m16 x 4 n16 over D[64b x 64n] ---
    const int wm = wid & 3;
    const int wn = wid >> 2;
    const int g  = lane >> 2;
    const int tk = lane & 3;
    const int rowA  = (wm * 16 + g) * ST_STRIDE;
    const int rowA8 = rowA + 8 * ST_STRIDE;

    // loop-invariant A fragments (T_h) in registers
    uint32_t afr[16][4];
    #pragma unroll
    for (int ks = 0; ks < 16; ks++) {
        const int c = ks * 8 + tk;
        afr[ks][0] = __float_as_uint(sT[rowA  + c]);
        afr[ks][1] = __float_as_uint(sT[rowA8 + c]);
        afr[ks][2] = __float_as_uint(sT[rowA  + c + 4]);
        afr[ks][3] = __float_as_uint(sT[rowA8 + c + 4]);
    }
    const float ar0 = sT[rowA  + 128];
    const float ar1 = sT[rowA8 + 128];

    float dacc[2][4];
    #pragma unroll
    for (int nj = 0; nj < 2; nj++)
        #pragma unroll
        for (int q = 0; q < 4; q++) dacc[nj][q] = 0.f;

    int fph0 = 0, fph1 = 0, fph2 = 0;
    int eph0 = 0, eph1 = 0, eph2 = 0;

    auto iter = [&](int r, int buf, int& fph, int& eph) {
        mbar_wait(FULLB(buf), fph); fph ^= 1;          // acquire: sB[buf] full
        const float* Bb = sm + SM_SB + buf * SB_FPB;

        float gacc[2][4];
        #pragma unroll
        for (int nj = 0; nj < 2; nj++)
            #pragma unroll
            for (int q = 0; q < 4; q++) gacc[nj][q] = 0.f;

        #pragma unroll
        for (int ks = 0; ks < 16; ks++) {
            #pragma unroll
            for (int nj = 0; nj < 2; nj++) {
                const int n = wn * 16 + nj * 8 + g;
                uint32_t b0 = to_tf32(Bb[(ks * 8 + tk)     * SB_STRIDE + n]);
                uint32_t b1 = to_tf32(Bb[(ks * 8 + 4 + tk) * SB_STRIDE + n]);
                mma_tf32(gacc[nj], afr[ks], b0, b1);
            }
        }
        // fp32 rank-1 for k=128 (raw W1 row 128)
        float2 w0 = *reinterpret_cast<const float2*>(Bb + 128 * SB_STRIDE + wn * 16 + 2 * tk);
        float2 w1 = *reinterpret_cast<const float2*>(Bb + 128 * SB_STRIDE + wn * 16 + 8 + 2 * tk);
        gacc[0][0] += ar0 * w0.x;  gacc[0][1] += ar0 * w0.y;
        gacc[0][2] += ar1 * w0.x;  gacc[0][3] += ar1 * w0.y;
        gacc[1][0] += ar0 * w1.x;  gacc[1][1] += ar0 * w1.y;
        gacc[1][2] += ar1 * w1.x;  gacc[1][3] += ar1 * w1.y;

        if (elect1()) mbar_arrive(EMPTYB(buf));        // release: done with sB[buf]

        // producer: refill this buffer for r+3 once all 16 warps released it
        if (wid == 0) {
            const int rn = r + 3;
            if (rn < nrows) {
                mbar_wait(EMPTYB(buf), eph); eph ^= 1;
                if (elect1()) mbar_expect_tx(FULLB(buf), R_BYTES);
                for (int row = lane; row < H1c; row += 32)
                    bulk_g2s(sb_u + buf * SB_BYTES + row * (SB_STRIDE * 4),
                             W1 + ((long long)(r0 + rn) * H1c + row) * N1,
                             N1 * 4, FULLB(buf));
            }
        }

        // epilogue: D += pm[r,row] * G (fp32; sPM untouched by ring)
        const float* pmr = sPM + r * Bq;
        float p0 = pmr[wm * 16 + g];
        float p1 = pmr[wm * 16 + g + 8];
        #pragma unroll
        for (int nj = 0; nj < 2; nj++) {
            dacc[nj][0] += p0 * gacc[nj][0];
            dacc[nj][1] += p0 * gacc[nj][1];
            dacc[nj][2] += p1 * gacc[nj][2];
            dacc[nj][3] += p1 * gacc[nj][3];
        }
    };

    for (int rb = 0; ; rb += 3) {               // unrolled by 3: static buf ids
        if (rb     >= nrows) break; iter(rb,     0, fph0, eph0);
        if (rb + 1 >= nrows) break; iter(rb + 1, 1, fph1, eph1);
        if (rb + 2 >= nrows) break; iter(rb + 2, 2, fph2, eph2);
    }

    // --- write partial tile: rows g,g+8; cols 2tk,2tk+1 within m16n16 ---
    float* basep = &g_partial[cta * (Bq * N1)];
    #pragma unroll
    for (int nj = 0; nj < 2; nj++) {
        const int rr = wm * 16 + g;
        const int n  = wn * 16 + nj * 8 + 2 * tk;
        *reinterpret_cast<float2*>(basep + rr * N1 + n) =
            make_float2(dacc[nj][0], dacc[nj][1]);
        *reinterpret_cast<float2*>(basep + (rr + 8) * N1 + n) =
            make_float2(dacc[nj][2], dacc[nj][3]);
    }
    #undef FULLB
    #undef EMPTYB
}

// ============================================================
// Kernel 2: reduce partials, +b1, relu -> g_Y1
// ============================================================
__global__ void k_reduce(const float* __restrict__ b1)
{
    int tix = blockIdx.x * blockDim.x + threadIdx.x;   // 0..4095
    float s = 0.f;
    #pragma unroll 4
    for (int c = 0; c < NCTA; c++)
        s += g_partial[c * (Bq * N1) + tix];
    s += b1[tix & (N1 - 1)];
    g_Y1[tix] = fmaxf(s, 0.f);
}

// ============================================================
// Kernel 3: tail MLP — 8-way ILP, 4 threads per batch row
// ============================================================
__global__ void k_tail(const float* __restrict__ W2, const float* __restrict__ b2,
                       const float* __restrict__ W3, const float* __restrict__ b3,
                       float* __restrict__ out)
{
    __shared__ float sW2[N1 * N2];
    __shared__ float sY1[Bq * 65];           // padded stride (bank spread)
    __shared__ float sW3[N2];
    __shared__ float sB2[N2];
    __shared__ float sred[256];
    int tid = threadIdx.x;
    for (int i = tid; i < N1 * N2; i += 256) sW2[i] = W2[i];
    for (int i = tid; i < Bq * N1; i += 256) {
        int b = i >> 6, o = i & 63;
        sY1[b * 65 + o] = g_Y1[i];
    }
    if (tid < N2) { sW3[tid] = W3[tid]; sB2[tid] = b2[tid]; }
    __syncthreads();

    const int b = tid >> 2;      // batch row
    const int q = tid & 3;       // j-quarter
    float s[8];
    #pragma unroll
    for (int jj = 0; jj < 8; jj++) s[jj] = sB2[q * 8 + jj];
    #pragma unroll 8
    for (int o = 0; o < N1; o++) {
        float y = sY1[b * 65 + o];
        #pragma unroll
        for (int jj = 0; jj < 8; jj++)
            s[jj] += y * sW2[o * N2 + q * 8 + jj];
    }
    float rq = 0.f;
    #pragma unroll
    for (int jj = 0; jj < 8; jj++) rq += fmaxf(s[jj], 0.f) * sW3[q * 8 + jj];
    sred[tid] = rq;
    __syncthreads();
    if (q == 0)
        out[b] = b3[0] + sred[tid] + sred[tid + 1] + sred[tid + 2] + sred[tid + 3];
}

// ============================================================
// Launch: v, a, t, W1, b1, W2, b2, W3, b3 ; out float[64]
// ============================================================
extern "C" void kernel_launch(void* const* d_in, const int* in_sizes, int n_in,
                              void* d_out, int out_size)
{
    const float *v  = (const float*)d_in[0];
    const float *a  = (const float*)d_in[1];
    const float *t  = (const float*)d_in[2];
    const float *W1 = (const float*)d_in[3];
    const float *b1 = (const float*)d_in[4];
    const float *W2 = (const float*)d_in[5];
    const float *b2 = (const float*)d_in[6];
    const float *W3 = (const float*)d_in[7];
    const float *b3 = (const float*)d_in[8];
    float *out = (float*)d_out;

    cudaFuncSetAttribute(k_main, cudaFuncAttributeMaxDynamicSharedMemorySize,
                         SM_FLOATS * 4);

    k_main<<<NCTA, NTHR, SM_FLOATS * 4>>>(v, a, t, W1);
    k_reduce<<<(Bq * N1) / 256, 256>>>(b1);
    k_tail<<<1, 256>>>(W2, b2, W3, b3, out);
}

// round 13
// speedup vs baseline: 3.9020x; 3.9020x over previous
#include <cuda_runtime.h>
#include <cuda_fp16.h>
#include <cstdint>

// ---------------- problem constants ----------------
#define Hc    128
#define H1c   129
#define NROW  (H1c*H1c)         // 16641 (i,j) rows, each 129 k long
#define Bq    64
#define N1    64
#define N2    32
#define NCTA  152               // 1 CTA per SM
#define NTHR  512               // 16 warps
#define RPC   110               // rows per CTA (151*110=16610; last CTA 31)

#define ST_STRIDE 132           // sT row stride (f32)
#define PH        72            // sH pitch in halves (64 + 8 pad): ldmatrix conflict-free
#define STG_F     (H1c*N1)      // 8256 floats per stage buf (33024 B)
#define SH_H      (Hc*PH)       // 9216 halves per sH buf (18432 B)

// smem layout (float offsets)
#define SM_T      0             // sT : 64 x 132 f32        = 8448
#define SM_PM     8448          // sPM: 110 x 64 f32        = 7040
#define SM_STAGE  15488         // stage: 3 x 8256 f32      = 24768
#define SM_H      40256         // sH : 2 x 9216 half       = 9216 (float units)
#define SM_MBAR   49472         // 3 mbarriers (6 floats)
#define SM_FLOATS 49478         // 197912 bytes

#define R_BYTES   (H1c * N1 * 4)    // 33024

__device__ float g_partial[NCTA * Bq * N1];
__device__ float g_Y1[Bq * N1];

// ---------------- helpers ----------------
__device__ __forceinline__ uint32_t smem_u32(const void* p) {
    uint32_t a;
    asm("{ .reg .u64 t; cvta.to.shared.u64 t, %1; cvt.u32.u64 %0, t; }" : "=r"(a) : "l"(p));
    return a;
}
__device__ __forceinline__ uint32_t packh2(float lo, float hi) {
    __half2 h = __floats2half2_rn(lo, hi);
    return *reinterpret_cast<uint32_t*>(&h);
}
__device__ __forceinline__ void mbar_init(uint32_t a, uint32_t cnt) {
    asm volatile("mbarrier.init.shared.b64 [%0], %1;" :: "r"(a), "r"(cnt) : "memory");
}
__device__ __forceinline__ void mbar_expect_tx(uint32_t a, uint32_t bytes) {
    asm volatile("mbarrier.arrive.expect_tx.shared.b64 _, [%0], %1;"
                 :: "r"(a), "r"(bytes) : "memory");
}
__device__ __forceinline__ void bulk_g2s(uint32_t dst, const void* src,
                                         uint32_t bytes, uint32_t mbar) {
    asm volatile(
        "cp.async.bulk.shared::cluster.global.mbarrier::complete_tx::bytes "
        "[%0], [%1], %2, [%3];"
        :: "r"(dst), "l"(src), "r"(bytes), "r"(mbar) : "memory");
}
__device__ __forceinline__ void mbar_wait(uint32_t a, uint32_t par) {
    uint32_t done;
    asm volatile("{\n\t.reg .pred p;\n\t"
                 "mbarrier.try_wait.parity.acquire.cta.shared::cta.b64 p, [%1], %2;\n\t"
                 "selp.b32 %0,1,0,p;\n\t}" : "=r"(done) : "r"(a), "r"(par) : "memory");
    if (!done) {
        asm volatile("{\n\t.reg .pred P1;\n\tW%=:\n\t"
                     "mbarrier.try_wait.parity.acquire.cta.shared::cta.b64 P1, [%0], %1, 0x989680;\n\t"
                     "@P1 bra.uni D%=;\n\tbra.uni W%=;\n\tD%=:\n\t}"
                     :: "r"(a), "r"(par) : "memory");
    }
}
// ldmatrix x4 transposed b16: 4 8x8 tiles -> B frags for 2 n8 columns
__device__ __forceinline__ void ldm_x4_trans(uint32_t& q0, uint32_t& q1,
                                             uint32_t& q2, uint32_t& q3,
                                             uint32_t addr) {
    asm volatile("ldmatrix.sync.aligned.m8n8.x4.trans.shared.b16 {%0,%1,%2,%3}, [%4];"
                 : "=r"(q0), "=r"(q1), "=r"(q2), "=r"(q3) : "r"(addr));
}
// D(16x8,f32) += A(16x16,f16) * B(16x8,f16)   row.col
__device__ __forceinline__ void mma_f16(float* d, const uint32_t* a,
                                        uint32_t b0, uint32_t b1) {
    asm volatile(
        "mma.sync.aligned.m16n8k16.row.col.f32.f16.f16.f32 "
        "{%0,%1,%2,%3}, {%4,%5,%6,%7}, {%8,%9}, {%0,%1,%2,%3};"
        : "+f"(d[0]), "+f"(d[1]), "+f"(d[2]), "+f"(d[3])
        : "r"(a[0]), "r"(a[1]), "r"(a[2]), "r"(a[3]), "r"(b0), "r"(b1));
}

// ============================================================
// Kernel 1: factored GEMM, fp16 mma + ldmatrix.trans.
//   per r:  G = T_h[64x129] @ W1_r[129x64]
//             = 8 x (m16n8k16 f16 MMA over k 0..127)  +  fp32 rank-1 (k=128)
//           D += pm[r,:] (x) G                          (fp32 epilogue)
// A (T_h) f16 frags in REGISTERS (loop-invariant).
// W1_r: one 33KB cp.async.bulk -> stage (3 slots, prefetch depth 2),
// then f32->f16 convert (no transpose) into sH (2 bufs, pitch 72 halves);
// ldmatrix.x4.trans does the k-pair transpose in HW, conflict-free.
// ============================================================
__global__ void __launch_bounds__(NTHR, 1)
k_main(const float* __restrict__ v, const float* __restrict__ a,
       const float* __restrict__ t, const float* __restrict__ W1)
{
    extern __shared__ float sm[];
    float* sT  = sm + SM_T;
    float* sPM = sm + SM_PM;
    const uint32_t base  = smem_u32(sm);
    const uint32_t stg_u = base + SM_STAGE * 4;
    const uint32_t sh_u  = base + SM_H * 4;
    const uint32_t mb[3] = { base + SM_MBAR * 4, base + SM_MBAR * 4 + 8,
                             base + SM_MBAR * 4 + 16 };

    const int tid  = threadIdx.x;
    const int wid  = tid >> 5;
    const int lane = tid & 31;
    const int cta  = blockIdx.x;

    const int r0    = cta * RPC;
    const int nrows = (r0 < NROW) ? min(RPC, NROW - r0) : 0;
    if (nrows <= 0) {
        float* out = &g_partial[cta * (Bq * N1)];
        for (int i = tid; i < Bq * N1; i += NTHR) out[i] = 0.f;
        return;
    }
    const int i0 = r0 / H1c;
    const int i1 = (r0 + nrows - 1) / H1c;

    // --- staging (in stage region, dead before first bulk): vT + a cols ---
    float* vT = sm + SM_STAGE;               // [c*65 + b]
    float* a2 = sm + SM_STAGE + 8320;        // [sel*64 + b]
    for (int idx = tid; idx < Bq * Hc; idx += NTHR) {
        int b = idx >> 7, c = idx & 127;
        vT[c * 65 + b] = v[idx];
    }
    if (tid < 128) {
        int c = tid >> 6, b = tid & 63;
        int ii = c ? i1 : i0;
        a2[c * 64 + b] = (ii == 0) ? 1.f : __ldg(&a[b * Hc + ii - 1]);
    }
    __syncthreads();

    // --- build pm slice (fp32) + sT (raw fp32; cvt to f16 at frag build) ---
    for (int idx = tid; idx < nrows * Bq; idx += NTHR) {
        int rloc = idx >> 6, b = idx & 63;
        int rg = r0 + rloc;
        int i  = rg / H1c;
        int j  = rg - i * H1c;
        float av = (i == i0) ? a2[b] : a2[64 + b];
        float vv = (j == 0) ? 1.f : vT[(j - 1) * 65 + b];
        sPM[idx] = av * vv;
    }
    for (int idx = tid; idx < Bq * H1c; idx += NTHR) {
        int b = idx / H1c;
        int c = idx - b * H1c;
        sT[b * ST_STRIDE + c] = (c == 0) ? 1.f : __ldg(&t[b * Hc + c - 1]);
    }
    if (tid == 0) { mbar_init(mb[0], 1); mbar_init(mb[1], 1); mbar_init(mb[2], 1); }
    __syncthreads();   // staging dead, sT/sPM/mbars live

    // --- prologue: prefetch slots 0,1 (depth 2) ---
    if (tid == 0) {
        mbar_expect_tx(mb[0], R_BYTES);
        bulk_g2s(stg_u, W1 + (long long)r0 * STG_F, R_BYTES, mb[0]);
        if (nrows > 1) {
            mbar_expect_tx(mb[1], R_BYTES);
            bulk_g2s(stg_u + STG_F * 4, W1 + (long long)(r0 + 1) * STG_F,
                     R_BYTES, mb[1]);
        }
    }

    // --- warp geometry: 16 warps = 4 m16 x 4 n16 over D[64b x 64n] ---
    const int wm = wid & 3;
    const int wn = wid >> 2;
    const int g  = lane >> 2;
    const int tk = lane & 3;
    const int m0 = wm * 16 + g;

    // --- loop-invariant A fragments (T_h), f16 in registers ---
    uint32_t afr[8][4];
    #pragma unroll
    for (int ks = 0; ks < 8; ks++) {
        const int c = ks * 16 + 2 * tk;
        const float* rA  = sT + m0 * ST_STRIDE;
        const float* rA8 = sT + (m0 + 8) * ST_STRIDE;
        afr[ks][0] = packh2(rA [c],     rA [c + 1]);
        afr[ks][1] = packh2(rA8[c],     rA8[c + 1]);
        afr[ks][2] = packh2(rA [c + 8], rA [c + 9]);
        afr[ks][3] = packh2(rA8[c + 8], rA8[c + 9]);
    }
    const float ar0 = sT[m0 * ST_STRIDE + 128];          // raw f32 T_h[.,128]
    const float ar1 = sT[(m0 + 8) * ST_STRIDE + 128];

    // ldmatrix lane address offset (within an sH buffer), bytes:
    //   matrices: sel bit0 = k-half (0/8), bit1 = nj (n offset 0/8)
    const int lrow = lane & 7;
    const int sel  = lane >> 3;
    const uint32_t lm_off =
        (uint32_t)((((sel & 1) * 8 + lrow) * PH + wn * 16 + (sel >> 1) * 8) * 2);

    float dacc[2][4];
    #pragma unroll
    for (int nj = 0; nj < 2; nj++)
        #pragma unroll
        for (int q = 0; q < 4; q++) dacc[nj][q] = 0.f;

    int ph[3] = {0, 0, 0};
    int sl = 0, sl2 = 2;                 // current slot, slot of r+2
    auto inc3 = [](int x) { return (x == 2) ? 0 : x + 1; };

    for (int r = 0; r < nrows; r++) {
        const int hb = r & 1;                          // sH buffer
        mbar_wait(mb[sl], ph[sl]); ph[sl] ^= 1;        // stage[sl] full

        // --- repack: stage[sl] f32 rows 0..127 -> sH[hb] f16 (no transpose) ---
        {
            const float* st = sm + SM_STAGE + sl * STG_F;
            __half* dh = reinterpret_cast<__half*>(sm + SM_H) + hb * SH_H;
            #pragma unroll
            for (int p = 0; p < 4; p++) {
                int idx = p * NTHR + tid;              // 0..2047
                int kk = idx >> 4, seg = idx & 15;
                float4 w = *reinterpret_cast<const float4*>(st + kk * 64 + seg * 4);
                uint2 u;
                u.x = packh2(w.x, w.y);
                u.y = packh2(w.z, w.w);
                *reinterpret_cast<uint2*>(dh + kk * PH + seg * 4) = u;
            }
        }
        __syncthreads();   // sH[hb] visible; everyone past MMA(r-1) -> stage[sl2] free
        if (tid == 0 && r + 2 < nrows) {
            mbar_expect_tx(mb[sl2], R_BYTES);
            bulk_g2s(stg_u + sl2 * (STG_F * 4),
                     W1 + (long long)(r0 + r + 2) * STG_F, R_BYTES, mb[sl2]);
        }

        // --- MMA: 8 f16 k16-steps (k 0..127) ---
        float gacc[2][4];
        #pragma unroll
        for (int nj = 0; nj < 2; nj++)
            #pragma unroll
            for (int q = 0; q < 4; q++) gacc[nj][q] = 0.f;

        const uint32_t ad = sh_u + hb * (SH_H * 2) + lm_off;
        #pragma unroll
        for (int ks = 0; ks < 8; ks++) {
            uint32_t q0, q1, q2, q3;
            ldm_x4_trans(q0, q1, q2, q3, ad + ks * (16 * PH * 2));
            mma_f16(gacc[0], afr[ks], q0, q1);
            mma_f16(gacc[1], afr[ks], q2, q3);
        }
        // fp32 rank-1 for k = 128 (raw f32 from stage[sl], broadcast loads)
        {
            const float* st = sm + SM_STAGE + sl * STG_F + 128 * 64;
            float2 w0 = *reinterpret_cast<const float2*>(st + wn * 16 + 2 * tk);
            float2 w1 = *reinterpret_cast<const float2*>(st + wn * 16 + 8 + 2 * tk);
            gacc[0][0] += ar0 * w0.x;  gacc[0][1] += ar0 * w0.y;
            gacc[0][2] += ar1 * w0.x;  gacc[0][3] += ar1 * w0.y;
            gacc[1][0] += ar0 * w1.x;  gacc[1][1] += ar0 * w1.y;
            gacc[1][2] += ar1 * w1.x;  gacc[1][3] += ar1 * w1.y;
        }
        // epilogue: D += pm[r,row] * G  (fp32)
        {
            const float* pmr = sPM + r * Bq;
            float p0 = pmr[m0];
            float p1 = pmr[m0 + 8];
            #pragma unroll
            for (int nj = 0; nj < 2; nj++) {
                dacc[nj][0] += p0 * gacc[nj][0];
                dacc[nj][1] += p0 * gacc[nj][1];
                dacc[nj][2] += p1 * gacc[nj][2];
                dacc[nj][3] += p1 * gacc[nj][3];
            }
        }
        sl = inc3(sl); sl2 = inc3(sl2);
    }

    // --- write partial tile: rows g,g+8; cols 2tk,2tk+1 within m16n16 ---
    float* basep = &g_partial[cta * (Bq * N1)];
    #pragma unroll
    for (int nj = 0; nj < 2; nj++) {
        const int n = wn * 16 + nj * 8 + 2 * tk;
        *reinterpret_cast<float2*>(basep + m0 * N1 + n) =
            make_float2(dacc[nj][0], dacc[nj][1]);
        *reinterpret_cast<float2*>(basep + (m0 + 8) * N1 + n) =
            make_float2(dacc[nj][2], dacc[nj][3]);
    }
}

// ============================================================
// Kernel 2: reduce partials, +b1, relu -> g_Y1
// ============================================================
__global__ void k_reduce(const float* __restrict__ b1)
{
    int tix = blockIdx.x * blockDim.x + threadIdx.x;   // 0..4095
    float s = 0.f;
    #pragma unroll 4
    for (int c = 0; c < NCTA; c++)
        s += g_partial[c * (Bq * N1) + tix];
    s += b1[tix & (N1 - 1)];
    g_Y1[tix] = fmaxf(s, 0.f);
}

// ============================================================
// Kernel 3: tail MLP — 8-way ILP, 4 threads per batch row
// ============================================================
__global__ void k_tail(const float* __restrict__ W2, const float* __restrict__ b2,
                       const float* __restrict__ W3, const float* __restrict__ b3,
                       float* __restrict__ out)
{
    __shared__ float sW2[N1 * N2];
    __shared__ float sY1[Bq * 65];
    __shared__ float sW3[N2];
    __shared__ float sB2[N2];
    __shared__ float sred[256];
    int tid = threadIdx.x;
    for (int i = tid; i < N1 * N2; i += 256) sW2[i] = W2[i];
    for (int i = tid; i < Bq * N1; i += 256) {
        int b = i >> 6, o = i & 63;
        sY1[b * 65 + o] = g_Y1[i];
    }
    if (tid < N2) { sW3[tid] = W3[tid]; sB2[tid] = b2[tid]; }
    __syncthreads();

    const int b = tid >> 2;
    const int q = tid & 3;
    float s[8];
    #pragma unroll
    for (int jj = 0; jj < 8; jj++) s[jj] = sB2[q * 8 + jj];
    #pragma unroll 8
    for (int o = 0; o < N1; o++) {
        float y = sY1[b * 65 + o];
        #pragma unroll
        for (int jj = 0; jj < 8; jj++)
            s[jj] += y * sW2[o * N2 + q * 8 + jj];
    }
    float rq = 0.f;
    #pragma unroll
    for (int jj = 0; jj < 8; jj++) rq += fmaxf(s[jj], 0.f) * sW3[q * 8 + jj];
    sred[tid] = rq;
    __syncthreads();
    if (q == 0)
        out[b] = b3[0] + sred[tid] + sred[tid + 1] + sred[tid + 2] + sred[tid + 3];
}

// ============================================================
// Launch: v, a, t, W1, b1, W2, b2, W3, b3 ; out float[64]
// ============================================================
extern "C" void kernel_launch(void* const* d_in, const int* in_sizes, int n_in,
                              void* d_out, int out_size)
{
    const float *v  = (const float*)d_in[0];
    const float *a  = (const float*)d_in[1];
    const float *t  = (const float*)d_in[2];
    const float *W1 = (const float*)d_in[3];
    const float *b1 = (const float*)d_in[4];
    const float *W2 = (const float*)d_in[5];
    const float *b2 = (const float*)d_in[6];
    const float *W3 = (const float*)d_in[7];
    const float *b3 = (const float*)d_in[8];
    float *out = (float*)d_out;

    cudaFuncSetAttribute(k_main, cudaFuncAttributeMaxDynamicSharedMemorySize,
                         SM_FLOATS * 4);

    k_main<<<NCTA, NTHR, SM_FLOATS * 4>>>(v, a, t, W1);
    k_reduce<<<(Bq * N1) / 256, 256>>>(b1);
    k_tail<<<1, 256>>>(W2, b2, W3, b3, out);
}

// round 14
// speedup vs baseline: 4.2925x; 1.1001x over previous
#include <cuda_runtime.h>
#include <cuda_fp16.h>
#include <cstdint>

// ---------------- problem constants ----------------
#define Hc    128
#define H1c   129
#define NROW  (H1c*H1c)         // 16641 (i,j) rows, each 129 k long
#define Bq    64
#define N1    64
#define N2    32
#define NCTA  152               // 1 CTA per SM
#define NTHR  512               // 16 warps
#define RPC   110               // rows per CTA (151*110=16610; last CTA 31)

#define ST_STRIDE 132           // sT row stride (f32)
#define PH        72            // sH pitch in halves (64 + 8 pad)
#define STG_F     (H1c*N1)      // 8256 floats per stage buf (33024 B)
#define SH_H      (Hc*PH)       // 9216 halves per sH buf (18432 B)

// smem layout (float offsets)
#define SM_T      0             // sT : 64 x 132 f32        = 8448
#define SM_PM     8448          // sPM: 110 x 64 f32        = 7040
#define SM_STAGE  15488         // stage: 3 x 8256 f32      = 24768
#define SM_H      40256         // sH : 2 x 9216 half       = 9216 (float units)
#define SM_MBAR   49472         // 3 mbarriers (6 floats)
#define SM_FLOATS 49478         // 197912 bytes

#define R_BYTES   (H1c * N1 * 4)    // 33024

__device__ float g_partial[NCTA * Bq * N1];

// ---------------- helpers ----------------
__device__ __forceinline__ uint32_t smem_u32(const void* p) {
    uint32_t a;
    asm("{ .reg .u64 t; cvta.to.shared.u64 t, %1; cvt.u32.u64 %0, t; }" : "=r"(a) : "l"(p));
    return a;
}
__device__ __forceinline__ uint32_t packh2(float lo, float hi) {
    __half2 h = __floats2half2_rn(lo, hi);
    return *reinterpret_cast<uint32_t*>(&h);
}
__device__ __forceinline__ void mbar_init(uint32_t a, uint32_t cnt) {
    asm volatile("mbarrier.init.shared.b64 [%0], %1;" :: "r"(a), "r"(cnt) : "memory");
}
__device__ __forceinline__ void mbar_expect_tx(uint32_t a, uint32_t bytes) {
    asm volatile("mbarrier.arrive.expect_tx.shared.b64 _, [%0], %1;"
                 :: "r"(a), "r"(bytes) : "memory");
}
__device__ __forceinline__ void bulk_g2s(uint32_t dst, const void* src,
                                         uint32_t bytes, uint32_t mbar) {
    asm volatile(
        "cp.async.bulk.shared::cluster.global.mbarrier::complete_tx::bytes "
        "[%0], [%1], %2, [%3];"
        :: "r"(dst), "l"(src), "r"(bytes), "r"(mbar) : "memory");
}
__device__ __forceinline__ void mbar_wait(uint32_t a, uint32_t par) {
    uint32_t done;
    asm volatile("{\n\t.reg .pred p;\n\t"
                 "mbarrier.try_wait.parity.acquire.cta.shared::cta.b64 p, [%1], %2;\n\t"
                 "selp.b32 %0,1,0,p;\n\t}" : "=r"(done) : "r"(a), "r"(par) : "memory");
    if (!done) {
        asm volatile("{\n\t.reg .pred P1;\n\tW%=:\n\t"
                     "mbarrier.try_wait.parity.acquire.cta.shared::cta.b64 P1, [%0], %1, 0x989680;\n\t"
                     "@P1 bra.uni D%=;\n\tbra.uni W%=;\n\tD%=:\n\t}"
                     :: "r"(a), "r"(par) : "memory");
    }
}
// ldmatrix x2 transposed b16: 2 8x8 tiles (k-halves) -> B frags for one n8 col
__device__ __forceinline__ void ldm_x2_trans(uint32_t& q0, uint32_t& q1, uint32_t addr) {
    asm volatile("ldmatrix.sync.aligned.m8n8.x2.trans.shared.b16 {%0,%1}, [%2];"
                 : "=r"(q0), "=r"(q1) : "r"(addr));
}
// D(16x8,f32) += A(16x16,f16) * B(16x8,f16)   row.col
__device__ __forceinline__ void mma_f16(float* d, const uint32_t* a,
                                        uint32_t b0, uint32_t b1) {
    asm volatile(
        "mma.sync.aligned.m16n8k16.row.col.f32.f16.f16.f32 "
        "{%0,%1,%2,%3}, {%4,%5,%6,%7}, {%8,%9}, {%0,%1,%2,%3};"
        : "+f"(d[0]), "+f"(d[1]), "+f"(d[2]), "+f"(d[3])
        : "r"(a[0]), "r"(a[1]), "r"(a[2]), "r"(a[3]), "r"(b0), "r"(b1));
}

// ============================================================
// Kernel 1: factored GEMM, fp16 mma + ldmatrix.x2.trans.
// Warp tiling 2(m32) x 8(n8): B-frag duplication 4x -> 2x
// (per-r L1 wavefronts drop below the DRAM share -> DRAM-bound).
// ============================================================
__global__ void __launch_bounds__(NTHR, 1)
k_main(const float* __restrict__ v, const float* __restrict__ a,
       const float* __restrict__ t, const float* __restrict__ W1)
{
    extern __shared__ float sm[];
    float* sT  = sm + SM_T;
    float* sPM = sm + SM_PM;
    const uint32_t base  = smem_u32(sm);
    const uint32_t stg_u = base + SM_STAGE * 4;
    const uint32_t sh_u  = base + SM_H * 4;
    const uint32_t mb[3] = { base + SM_MBAR * 4, base + SM_MBAR * 4 + 8,
                             base + SM_MBAR * 4 + 16 };

    const int tid  = threadIdx.x;
    const int wid  = tid >> 5;
    const int lane = tid & 31;
    const int cta  = blockIdx.x;

    const int r0    = cta * RPC;
    const int nrows = (r0 < NROW) ? min(RPC, NROW - r0) : 0;
    if (nrows <= 0) {
        float* out = &g_partial[cta * (Bq * N1)];
        for (int i = tid; i < Bq * N1; i += NTHR) out[i] = 0.f;
        return;
    }
    const int i0 = r0 / H1c;
    const int i1 = (r0 + nrows - 1) / H1c;

    // --- staging (stage region, dead before first bulk): vT + a cols ---
    float* vT = sm + SM_STAGE;               // [c*65 + b]
    float* a2 = sm + SM_STAGE + 8320;        // [sel*64 + b]
    for (int idx = tid; idx < Bq * Hc; idx += NTHR) {
        int b = idx >> 7, c = idx & 127;
        vT[c * 65 + b] = v[idx];
    }
    if (tid < 128) {
        int c = tid >> 6, b = tid & 63;
        int ii = c ? i1 : i0;
        a2[c * 64 + b] = (ii == 0) ? 1.f : __ldg(&a[b * Hc + ii - 1]);
    }
    __syncthreads();

    // --- build pm slice (fp32) + sT (raw fp32) ---
    for (int idx = tid; idx < nrows * Bq; idx += NTHR) {
        int rloc = idx >> 6, b = idx & 63;
        int rg = r0 + rloc;
        int i  = rg / H1c;
        int j  = rg - i * H1c;
        float av = (i == i0) ? a2[b] : a2[64 + b];
        float vv = (j == 0) ? 1.f : vT[(j - 1) * 65 + b];
        sPM[idx] = av * vv;
    }
    for (int idx = tid; idx < Bq * H1c; idx += NTHR) {
        int b = idx / H1c;
        int c = idx - b * H1c;
        sT[b * ST_STRIDE + c] = (c == 0) ? 1.f : __ldg(&t[b * Hc + c - 1]);
    }
    if (tid == 0) { mbar_init(mb[0], 1); mbar_init(mb[1], 1); mbar_init(mb[2], 1); }
    __syncthreads();

    // --- prologue: prefetch slots 0,1 ---
    if (tid == 0) {
        mbar_expect_tx(mb[0], R_BYTES);
        bulk_g2s(stg_u, W1 + (long long)r0 * STG_F, R_BYTES, mb[0]);
        if (nrows > 1) {
            mbar_expect_tx(mb[1], R_BYTES);
            bulk_g2s(stg_u + STG_F * 4, W1 + (long long)(r0 + 1) * STG_F,
                     R_BYTES, mb[1]);
        }
    }

    // --- warp geometry: 16 warps = 2 m32 x 8 n8 over D[64b x 64n] ---
    const int wm = wid & 1;           // m32 block
    const int wn = wid >> 1;          // n8 column (0..7)
    const int g  = lane >> 2;
    const int tk = lane & 3;

    // --- loop-invariant A fragments (T_h), f16, 2 m16 tiles ---
    uint32_t afr[8][2][4];
    float ar[2][2];
    #pragma unroll
    for (int mi = 0; mi < 2; mi++) {
        const int mrow = wm * 32 + mi * 16 + g;
        const float* rA  = sT + mrow * ST_STRIDE;
        const float* rA8 = sT + (mrow + 8) * ST_STRIDE;
        #pragma unroll
        for (int ks = 0; ks < 8; ks++) {
            const int c = ks * 16 + 2 * tk;
            afr[ks][mi][0] = packh2(rA [c],     rA [c + 1]);
            afr[ks][mi][1] = packh2(rA8[c],     rA8[c + 1]);
            afr[ks][mi][2] = packh2(rA [c + 8], rA [c + 9]);
            afr[ks][mi][3] = packh2(rA8[c + 8], rA8[c + 9]);
        }
        ar[mi][0] = rA [128];
        ar[mi][1] = rA8[128];
    }

    // ldmatrix x2 lane address (lanes 0-15 used; 16-31 mirror)
    const int lrow = lane & 7;
    const int sel  = (lane >> 3) & 1;              // k-half
    const uint32_t lm_off = (uint32_t)(((sel * 8 + lrow) * PH + wn * 8) * 2);

    float dacc[2][4];
    #pragma unroll
    for (int mi = 0; mi < 2; mi++)
        #pragma unroll
        for (int q = 0; q < 4; q++) dacc[mi][q] = 0.f;

    int ph[3] = {0, 0, 0};
    int sl = 0, sl2 = 2;
    auto inc3 = [](int x) { return (x == 2) ? 0 : x + 1; };

    for (int r = 0; r < nrows; r++) {
        const int hb = r & 1;
        mbar_wait(mb[sl], ph[sl]); ph[sl] ^= 1;        // stage[sl] full

        // --- repack: stage f32 rows 0..127 -> sH[hb] f16 ---
        {
            const float* st = sm + SM_STAGE + sl * STG_F;
            __half* dh = reinterpret_cast<__half*>(sm + SM_H) + hb * SH_H;
            #pragma unroll
            for (int p = 0; p < 4; p++) {
                int idx = p * NTHR + tid;              // 0..2047
                int kk = idx >> 4, seg = idx & 15;
                float4 w = *reinterpret_cast<const float4*>(st + kk * 64 + seg * 4);
                uint2 u;
                u.x = packh2(w.x, w.y);
                u.y = packh2(w.z, w.w);
                *reinterpret_cast<uint2*>(dh + kk * PH + seg * 4) = u;
            }
        }
        __syncthreads();   // sH[hb] visible; all warps past MMA(r-1)
        if (tid == 0 && r + 2 < nrows) {
            mbar_expect_tx(mb[sl2], R_BYTES);
            bulk_g2s(stg_u + sl2 * (STG_F * 4),
                     W1 + (long long)(r0 + r + 2) * STG_F, R_BYTES, mb[sl2]);
        }

        // --- MMA: 8 f16 k16-steps, one n8 column, two m16 tiles ---
        float gacc[2][4];
        #pragma unroll
        for (int mi = 0; mi < 2; mi++)
            #pragma unroll
            for (int q = 0; q < 4; q++) gacc[mi][q] = 0.f;

        const uint32_t ad = sh_u + hb * (SH_H * 2) + lm_off;
        #pragma unroll
        for (int ks = 0; ks < 8; ks++) {
            uint32_t q0, q1;
            ldm_x2_trans(q0, q1, ad + ks * (16 * PH * 2));
            mma_f16(gacc[0], afr[ks][0], q0, q1);
            mma_f16(gacc[1], afr[ks][1], q0, q1);
        }
        // fp32 rank-1 for k = 128 (raw f32 from stage[sl])
        {
            const float* st = sm + SM_STAGE + sl * STG_F + 128 * 64;
            float2 w0 = *reinterpret_cast<const float2*>(st + wn * 8 + 2 * tk);
            #pragma unroll
            for (int mi = 0; mi < 2; mi++) {
                gacc[mi][0] += ar[mi][0] * w0.x;  gacc[mi][1] += ar[mi][0] * w0.y;
                gacc[mi][2] += ar[mi][1] * w0.x;  gacc[mi][3] += ar[mi][1] * w0.y;
            }
        }
        // epilogue: D += pm[r,row] * G  (fp32)
        {
            const float* pmr = sPM + r * Bq;
            #pragma unroll
            for (int mi = 0; mi < 2; mi++) {
                const int mrow = wm * 32 + mi * 16 + g;
                float p0 = pmr[mrow];
                float p1 = pmr[mrow + 8];
                dacc[mi][0] += p0 * gacc[mi][0];
                dacc[mi][1] += p0 * gacc[mi][1];
                dacc[mi][2] += p1 * gacc[mi][2];
                dacc[mi][3] += p1 * gacc[mi][3];
            }
        }
        sl = inc3(sl); sl2 = inc3(sl2);
    }

    // --- write partial tile ---
    float* basep = &g_partial[cta * (Bq * N1)];
    #pragma unroll
    for (int mi = 0; mi < 2; mi++) {
        const int mrow = wm * 32 + mi * 16 + g;
        const int n = wn * 8 + 2 * tk;
        *reinterpret_cast<float2*>(basep + mrow * N1 + n) =
            make_float2(dacc[mi][0], dacc[mi][1]);
        *reinterpret_cast<float2*>(basep + (mrow + 8) * N1 + n) =
            make_float2(dacc[mi][2], dacc[mi][3]);
    }
}

// ============================================================
// Kernel 2: fused reduce + tail MLP.
// 16 CTAs x 256 thr; CTA owns 4 batch rows end-to-end:
//   sum 152 partials -> +b1, relu -> smem Y1 row
//   layer2 (32 j x 2 o-halves) -> relu -> W3 dot via warp shuffle -> out[b]
// ============================================================
__global__ void k_final(const float* __restrict__ b1, const float* __restrict__ W2,
                        const float* __restrict__ b2, const float* __restrict__ W3,
                        const float* __restrict__ b3, float* __restrict__ out)
{
    __shared__ float sY1[4][65];
    __shared__ float sW2[N1 * N2];
    __shared__ float sW3[N2];
    __shared__ float sB2[N2];
    __shared__ float sred[256];
    const int tid = threadIdx.x;

    for (int i = tid; i < N1 * N2; i += 256) sW2[i] = W2[i];
    if (tid < N2) { sW3[tid] = W3[tid]; sB2[tid] = b2[tid]; }

    const int b  = tid >> 6;                 // 0..3 local batch
    const int o  = tid & 63;
    const int gb = blockIdx.x * 4 + b;       // global batch row

    float s = 0.f;
    #pragma unroll 8
    for (int c = 0; c < NCTA; c++)
        s += g_partial[c * (Bq * N1) + gb * N1 + o];
    s += b1[o];
    sY1[b][o] = fmaxf(s, 0.f);
    __syncthreads();

    const int j    = tid & 31;               // output unit of layer 2
    const int half = (tid >> 5) & 1;         // o-half
    float acc = 0.f;
    #pragma unroll
    for (int o2 = 0; o2 < 32; o2++)
        acc += sY1[b][half * 32 + o2] * sW2[(half * 32 + o2) * N2 + j];
    sred[tid] = acc;
    __syncthreads();

    if (half == 0) {                          // tids b*64+j, j<32: one full warp
        float y2 = fmaxf(acc + sred[tid + 32] + sB2[j], 0.f);
        float contrib = y2 * sW3[j];
        #pragma unroll
        for (int off = 16; off; off >>= 1)
            contrib += __shfl_down_sync(0xFFFFFFFFu, contrib, off);
        if (j == 0) out[gb] = contrib + b3[0];
    }
}

// ============================================================
// Launch: v, a, t, W1, b1, W2, b2, W3, b3 ; out float[64]
// ============================================================
extern "C" void kernel_launch(void* const* d_in, const int* in_sizes, int n_in,
                              void* d_out, int out_size)
{
    const float *v  = (const float*)d_in[0];
    const float *a  = (const float*)d_in[1];
    const float *t  = (const float*)d_in[2];
    const float *W1 = (const float*)d_in[3];
    const float *b1 = (const float*)d_in[4];
    const float *W2 = (const float*)d_in[5];
    const float *b2 = (const float*)d_in[6];
    const float *W3 = (const float*)d_in[7];
    const float *b3 = (const float*)d_in[8];
    float *out = (float*)d_out;

    cudaFuncSetAttribute(k_main, cudaFuncAttributeMaxDynamicSharedMemorySize,
                         SM_FLOATS * 4);

    k_main<<<NCTA, NTHR, SM_FLOATS * 4>>>(v, a, t, W1);
    k_final<<<Bq / 4, 256>>>(b1, W2, b2, W3, b3, out);
}

// round 15
// speedup vs baseline: 4.3685x; 1.0177x over previous
#include <cuda_runtime.h>
#include <cuda_fp16.h>
#include <cstdint>

// ---------------- problem constants ----------------
#define Hc    128
#define H1c   129
#define NROW  (H1c*H1c)         // 16641 (i,j) rows, each 129 k long
#define Bq    64
#define N1    64
#define N2    32
#define NCTA  152               // 1 CTA per SM
#define NTHR  512               // 16 warps
#define RPC   110               // rows per CTA (151*110=16610; last CTA 31)

#define ST_STRIDE 132           // sT row stride (f32)
#define PH        72            // sH pitch in halves (64 + 8 pad)
#define STG_F     (H1c*N1)      // 8256 floats per stage buf (33024 B)
#define SH_H      (Hc*PH)       // 9216 halves per sH buf (18432 B)

// smem layout (float offsets)
#define SM_T      0             // sT : 64 x 132 f32        = 8448
#define SM_PM     8448          // sPM: 110 x 64 f32        = 7040
#define SM_STAGE  15488         // stage: 3 x 8256 f32      = 24768
#define SM_H      40256         // sH : 2 x 9216 half       = 9216 (float units)
#define SM_MBAR   49472         // 3 mbarriers (6 floats)
#define SM_FLOATS 49478         // 197912 bytes

#define R_BYTES   (H1c * N1 * 4)    // 33024

__device__ float    g_Y1pre[Bq * N1];   // accumulated via REDG; zero-init, self-cleaning
__device__ unsigned g_ctr;              // last-CTA counter; zero-init, self-cleaning

// ---------------- helpers ----------------
__device__ __forceinline__ uint32_t smem_u32(const void* p) {
    uint32_t a;
    asm("{ .reg .u64 t; cvta.to.shared.u64 t, %1; cvt.u32.u64 %0, t; }" : "=r"(a) : "l"(p));
    return a;
}
__device__ __forceinline__ uint32_t packh2(float lo, float hi) {
    __half2 h = __floats2half2_rn(lo, hi);
    return *reinterpret_cast<uint32_t*>(&h);
}
__device__ __forceinline__ void mbar_init(uint32_t a, uint32_t cnt) {
    asm volatile("mbarrier.init.shared.b64 [%0], %1;" :: "r"(a), "r"(cnt) : "memory");
}
__device__ __forceinline__ void mbar_expect_tx(uint32_t a, uint32_t bytes) {
    asm volatile("mbarrier.arrive.expect_tx.shared.b64 _, [%0], %1;"
                 :: "r"(a), "r"(bytes) : "memory");
}
__device__ __forceinline__ void bulk_g2s(uint32_t dst, const void* src,
                                         uint32_t bytes, uint32_t mbar) {
    asm volatile(
        "cp.async.bulk.shared::cluster.global.mbarrier::complete_tx::bytes "
        "[%0], [%1], %2, [%3];"
        :: "r"(dst), "l"(src), "r"(bytes), "r"(mbar) : "memory");
}
__device__ __forceinline__ void mbar_wait(uint32_t a, uint32_t par) {
    uint32_t done;
    asm volatile("{\n\t.reg .pred p;\n\t"
                 "mbarrier.try_wait.parity.acquire.cta.shared::cta.b64 p, [%1], %2;\n\t"
                 "selp.b32 %0,1,0,p;\n\t}" : "=r"(done) : "r"(a), "r"(par) : "memory");
    if (!done) {
        asm volatile("{\n\t.reg .pred P1;\n\tW%=:\n\t"
                     "mbarrier.try_wait.parity.acquire.cta.shared::cta.b64 P1, [%0], %1, 0x989680;\n\t"
                     "@P1 bra.uni D%=;\n\tbra.uni W%=;\n\tD%=:\n\t}"
                     :: "r"(a), "r"(par) : "memory");
    }
}
__device__ __forceinline__ void ldm_x2_trans(uint32_t& q0, uint32_t& q1, uint32_t addr) {
    asm volatile("ldmatrix.sync.aligned.m8n8.x2.trans.shared.b16 {%0,%1}, [%2];"
                 : "=r"(q0), "=r"(q1) : "r"(addr));
}
__device__ __forceinline__ void mma_f16(float* d, const uint32_t* a,
                                        uint32_t b0, uint32_t b1) {
    asm volatile(
        "mma.sync.aligned.m16n8k16.row.col.f32.f16.f16.f32 "
        "{%0,%1,%2,%3}, {%4,%5,%6,%7}, {%8,%9}, {%0,%1,%2,%3};"
        : "+f"(d[0]), "+f"(d[1]), "+f"(d[2]), "+f"(d[3])
        : "r"(a[0]), "r"(a[1]), "r"(a[2]), "r"(a[3]), "r"(b0), "r"(b1));
}

// ============================================================
// Kernel: factored GEMM (fp16 mma + ldmatrix.x2.trans, 2m32 x 8n8 tiling)
// + REDG accumulation into g_Y1pre + last-CTA fused reduce/tail-MLP.
// ============================================================
__global__ void __launch_bounds__(NTHR, 1)
k_main(const float* __restrict__ v, const float* __restrict__ a,
       const float* __restrict__ t, const float* __restrict__ W1,
       const float* __restrict__ b1, const float* __restrict__ W2,
       const float* __restrict__ b2, const float* __restrict__ W3,
       const float* __restrict__ b3, float* __restrict__ out)
{
    extern __shared__ float sm[];
    float* sT  = sm + SM_T;
    float* sPM = sm + SM_PM;
    const uint32_t base  = smem_u32(sm);
    const uint32_t stg_u = base + SM_STAGE * 4;
    const uint32_t sh_u  = base + SM_H * 4;
    const uint32_t mb[3] = { base + SM_MBAR * 4, base + SM_MBAR * 4 + 8,
                             base + SM_MBAR * 4 + 16 };

    const int tid  = threadIdx.x;
    const int wid  = tid >> 5;
    const int lane = tid & 31;
    const int cta  = blockIdx.x;

    const int r0    = cta * RPC;
    const int nrows = (r0 < NROW) ? min(RPC, NROW - r0) : 0;

    if (nrows > 0) {
        const int i0 = r0 / H1c;
        const int i1 = (r0 + nrows - 1) / H1c;

        // --- staging (stage region, dead before first bulk): vT + a cols ---
        float* vT = sm + SM_STAGE;               // [c*65 + b]
        float* a2 = sm + SM_STAGE + 8320;        // [sel*64 + b]
        for (int idx = tid; idx < Bq * Hc; idx += NTHR) {
            int b = idx >> 7, c = idx & 127;
            vT[c * 65 + b] = v[idx];
        }
        if (tid < 128) {
            int c = tid >> 6, b = tid & 63;
            int ii = c ? i1 : i0;
            a2[c * 64 + b] = (ii == 0) ? 1.f : __ldg(&a[b * Hc + ii - 1]);
        }
        __syncthreads();

        // --- build pm slice (fp32) + sT (raw fp32) ---
        for (int idx = tid; idx < nrows * Bq; idx += NTHR) {
            int rloc = idx >> 6, b = idx & 63;
            int rg = r0 + rloc;
            int i  = rg / H1c;
            int j  = rg - i * H1c;
            float av = (i == i0) ? a2[b] : a2[64 + b];
            float vv = (j == 0) ? 1.f : vT[(j - 1) * 65 + b];
            sPM[idx] = av * vv;
        }
        for (int idx = tid; idx < Bq * H1c; idx += NTHR) {
            int b = idx / H1c;
            int c = idx - b * H1c;
            sT[b * ST_STRIDE + c] = (c == 0) ? 1.f : __ldg(&t[b * Hc + c - 1]);
        }
        if (tid == 0) { mbar_init(mb[0], 1); mbar_init(mb[1], 1); mbar_init(mb[2], 1); }
        __syncthreads();

        // --- prologue: prefetch slots 0,1 ---
        if (tid == 0) {
            mbar_expect_tx(mb[0], R_BYTES);
            bulk_g2s(stg_u, W1 + (long long)r0 * STG_F, R_BYTES, mb[0]);
            if (nrows > 1) {
                mbar_expect_tx(mb[1], R_BYTES);
                bulk_g2s(stg_u + STG_F * 4, W1 + (long long)(r0 + 1) * STG_F,
                         R_BYTES, mb[1]);
            }
        }

        // --- warp geometry: 16 warps = 2 m32 x 8 n8 over D[64b x 64n] ---
        const int wm = wid & 1;
        const int wn = wid >> 1;
        const int g  = lane >> 2;
        const int tk = lane & 3;

        uint32_t afr[8][2][4];
        float ar[2][2];
        #pragma unroll
        for (int mi = 0; mi < 2; mi++) {
            const int mrow = wm * 32 + mi * 16 + g;
            const float* rA  = sT + mrow * ST_STRIDE;
            const float* rA8 = sT + (mrow + 8) * ST_STRIDE;
            #pragma unroll
            for (int ks = 0; ks < 8; ks++) {
                const int c = ks * 16 + 2 * tk;
                afr[ks][mi][0] = packh2(rA [c],     rA [c + 1]);
                afr[ks][mi][1] = packh2(rA8[c],     rA8[c + 1]);
                afr[ks][mi][2] = packh2(rA [c + 8], rA [c + 9]);
                afr[ks][mi][3] = packh2(rA8[c + 8], rA8[c + 9]);
            }
            ar[mi][0] = rA [128];
            ar[mi][1] = rA8[128];
        }

        const int lrow = lane & 7;
        const int sel  = (lane >> 3) & 1;
        const uint32_t lm_off = (uint32_t)(((sel * 8 + lrow) * PH + wn * 8) * 2);

        float dacc[2][4];
        #pragma unroll
        for (int mi = 0; mi < 2; mi++)
            #pragma unroll
            for (int q = 0; q < 4; q++) dacc[mi][q] = 0.f;

        int ph[3] = {0, 0, 0};
        int sl = 0, sl2 = 2;
        auto inc3 = [](int x) { return (x == 2) ? 0 : x + 1; };

        for (int r = 0; r < nrows; r++) {
            const int hb = r & 1;
            mbar_wait(mb[sl], ph[sl]); ph[sl] ^= 1;        // stage[sl] full

            // repack: stage f32 rows 0..127 -> sH[hb] f16
            {
                const float* st = sm + SM_STAGE + sl * STG_F;
                __half* dh = reinterpret_cast<__half*>(sm + SM_H) + hb * SH_H;
                #pragma unroll
                for (int p = 0; p < 4; p++) {
                    int idx = p * NTHR + tid;
                    int kk = idx >> 4, seg = idx & 15;
                    float4 w = *reinterpret_cast<const float4*>(st + kk * 64 + seg * 4);
                    uint2 u;
                    u.x = packh2(w.x, w.y);
                    u.y = packh2(w.z, w.w);
                    *reinterpret_cast<uint2*>(dh + kk * PH + seg * 4) = u;
                }
            }
            __syncthreads();
            if (tid == 0 && r + 2 < nrows) {
                mbar_expect_tx(mb[sl2], R_BYTES);
                bulk_g2s(stg_u + sl2 * (STG_F * 4),
                         W1 + (long long)(r0 + r + 2) * STG_F, R_BYTES, mb[sl2]);
            }

            // MMA: 8 f16 k16-steps
            float gacc[2][4];
            #pragma unroll
            for (int mi = 0; mi < 2; mi++)
                #pragma unroll
                for (int q = 0; q < 4; q++) gacc[mi][q] = 0.f;

            const uint32_t ad = sh_u + hb * (SH_H * 2) + lm_off;
            #pragma unroll
            for (int ks = 0; ks < 8; ks++) {
                uint32_t q0, q1;
                ldm_x2_trans(q0, q1, ad + ks * (16 * PH * 2));
                mma_f16(gacc[0], afr[ks][0], q0, q1);
                mma_f16(gacc[1], afr[ks][1], q0, q1);
            }
            // fp32 rank-1 for k = 128
            {
                const float* st = sm + SM_STAGE + sl * STG_F + 128 * 64;
                float2 w0 = *reinterpret_cast<const float2*>(st + wn * 8 + 2 * tk);
                #pragma unroll
                for (int mi = 0; mi < 2; mi++) {
                    gacc[mi][0] += ar[mi][0] * w0.x;  gacc[mi][1] += ar[mi][0] * w0.y;
                    gacc[mi][2] += ar[mi][1] * w0.x;  gacc[mi][3] += ar[mi][1] * w0.y;
                }
            }
            // epilogue: D += pm[r,row] * G
            {
                const float* pmr = sPM + r * Bq;
                #pragma unroll
                for (int mi = 0; mi < 2; mi++) {
                    const int mrow = wm * 32 + mi * 16 + g;
                    float p0 = pmr[mrow];
                    float p1 = pmr[mrow + 8];
                    dacc[mi][0] += p0 * gacc[mi][0];
                    dacc[mi][1] += p0 * gacc[mi][1];
                    dacc[mi][2] += p1 * gacc[mi][2];
                    dacc[mi][3] += p1 * gacc[mi][3];
                }
            }
            sl = inc3(sl); sl2 = inc3(sl2);
        }

        // --- accumulate into global Y1pre via REDG (no return) ---
        #pragma unroll
        for (int mi = 0; mi < 2; mi++) {
            const int mrow = wm * 32 + mi * 16 + g;
            const int n = wn * 8 + 2 * tk;
            atomicAdd(&g_Y1pre[mrow * N1 + n],           dacc[mi][0]);
            atomicAdd(&g_Y1pre[mrow * N1 + n + 1],       dacc[mi][1]);
            atomicAdd(&g_Y1pre[(mrow + 8) * N1 + n],     dacc[mi][2]);
            atomicAdd(&g_Y1pre[(mrow + 8) * N1 + n + 1], dacc[mi][3]);
        }
    }

    // ---- last-CTA fused reduce + tail MLP ----
    __threadfence();
    __shared__ unsigned s_last;
    if (tid == 0) s_last = (atomicAdd(&g_ctr, 1u) == (unsigned)(gridDim.x - 1));
    __syncthreads();
    if (!s_last) return;

    // reuse dynamic smem (all prior uses dead)
    float* sY1 = sm;                 // [b*65 + o], 4160 floats
    float* sW2 = sm + 4160;          // 2048
    float* sW3 = sm + 6208;          // 32
    float* sB2 = sm + 6240;          // 32

    for (int i = tid; i < N1 * N2; i += NTHR) sW2[i] = __ldg(&W2[i]);
    if (tid < N2) { sW3[tid] = __ldg(&W3[tid]); sB2[tid] = __ldg(&b2[tid]); }
    for (int i = tid; i < Bq * N1; i += NTHR) {
        int b = i >> 6, o = i & 63;
        float s;
        asm volatile("ld.global.cg.f32 %0, [%1];" : "=f"(s) : "l"(g_Y1pre + i));
        sY1[b * 65 + o] = fmaxf(s + __ldg(&b1[o]), 0.f);
    }
    __syncthreads();

    // 8 threads per batch row; each computes 4 layer-2 units
    {
        const int b = tid >> 3;          // 0..63
        const int q = tid & 7;           // j-octant
        float s4[4];
        #pragma unroll
        for (int jj = 0; jj < 4; jj++) s4[jj] = sB2[q * 4 + jj];
        #pragma unroll 8
        for (int o = 0; o < N1; o++) {
            float y = sY1[b * 65 + o];
            #pragma unroll
            for (int jj = 0; jj < 4; jj++)
                s4[jj] += y * sW2[o * N2 + q * 4 + jj];
        }
        float rq = 0.f;
        #pragma unroll
        for (int jj = 0; jj < 4; jj++)
            rq += fmaxf(s4[jj], 0.f) * sW3[q * 4 + jj];
        #pragma unroll
        for (int off = 4; off; off >>= 1)
            rq += __shfl_down_sync(0xFFFFFFFFu, rq, off, 8);
        if (q == 0) out[b] = rq + __ldg(&b3[0]);
    }
    __syncthreads();

    // self-clean for graph replay: zero accumulator, reset counter
    for (int i = tid; i < Bq * N1; i += NTHR) g_Y1pre[i] = 0.f;
    if (tid == 0) g_ctr = 0u;
}

// ============================================================
// Launch: v, a, t, W1, b1, W2, b2, W3, b3 ; out float[64]
// ============================================================
extern "C" void kernel_launch(void* const* d_in, const int* in_sizes, int n_in,
                              void* d_out, int out_size)
{
    const float *v  = (const float*)d_in[0];
    const float *a  = (const float*)d_in[1];
    const float *t  = (const float*)d_in[2];
    const float *W1 = (const float*)d_in[3];
    const float *b1 = (const float*)d_in[4];
    const float *W2 = (const float*)d_in[5];
    const float *b2 = (const float*)d_in[6];
    const float *W3 = (const float*)d_in[7];
    const float *b3 = (const float*)d_in[8];
    float *out = (float*)d_out;

    cudaFuncSetAttribute(k_main, cudaFuncAttributeMaxDynamicSharedMemorySize,
                         SM_FLOATS * 4);

    k_main<<<NCTA, NTHR, SM_FLOATS * 4>>>(v, a, t, W1, b1, W2, b2, W3, b3, out);
}

// round 16
// speedup vs baseline: 4.6402x; 1.0622x over previous
#include <cuda_runtime.h>
#include <cuda_fp16.h>
#include <cstdint>

// ---------------- problem constants ----------------
#define Hc    128
#define H1c   129
#define NROW  (H1c*H1c)         // 16641 (i,j) rows, each 129 k long
#define Bq    64
#define N1    64
#define N2    32
#define NCTA  304               // 2 CTAs per SM
#define NTHR  256               // 8 warps
#define RPC   55                // rows per CTA (304*55 = 16720 >= 16641)

#define ST_STRIDE 132           // sT row stride (f32, staged)
#define PH        72            // sH pitch in halves (64 + 8 pad)
#define STG_F     (H1c*N1)      // 8256 floats per stage slot (33024 B)
#define SH_H      (Hc*PH)       // 9216 halves (single sH buf, 18432 B)

// smem layout (float offsets)                     bytes
#define SM_PM     0             // sPM: 55 x 64     14080
#define SM_STAGE  3520          // stage: 2 x 8256  66048
#define SM_H      20032         // sH: 4608 f       18432
#define SM_MBAR   24640         // 2 mbarriers          16
#define SM_FLOATS 24644         // 98576 B/CTA (x2 = 197152 <= 227KB)

#define R_BYTES   (H1c * N1 * 4)    // 33024

__device__ float    g_Y1pre[Bq * N1];   // REDG accumulator; zero-init, self-cleaning
__device__ unsigned g_ctr;              // last-CTA counter; zero-init, self-cleaning

// ---------------- helpers ----------------
__device__ __forceinline__ uint32_t smem_u32(const void* p) {
    uint32_t a;
    asm("{ .reg .u64 t; cvta.to.shared.u64 t, %1; cvt.u32.u64 %0, t; }" : "=r"(a) : "l"(p));
    return a;
}
__device__ __forceinline__ uint32_t packh2(float lo, float hi) {
    __half2 h = __floats2half2_rn(lo, hi);
    return *reinterpret_cast<uint32_t*>(&h);
}
__device__ __forceinline__ void mbar_init(uint32_t a, uint32_t cnt) {
    asm volatile("mbarrier.init.shared.b64 [%0], %1;" :: "r"(a), "r"(cnt) : "memory");
}
__device__ __forceinline__ void mbar_expect_tx(uint32_t a, uint32_t bytes) {
    asm volatile("mbarrier.arrive.expect_tx.shared.b64 _, [%0], %1;"
                 :: "r"(a), "r"(bytes) : "memory");
}
__device__ __forceinline__ void bulk_g2s(uint32_t dst, const void* src,
                                         uint32_t bytes, uint32_t mbar) {
    asm volatile(
        "cp.async.bulk.shared::cluster.global.mbarrier::complete_tx::bytes "
        "[%0], [%1], %2, [%3];"
        :: "r"(dst), "l"(src), "r"(bytes), "r"(mbar) : "memory");
}
__device__ __forceinline__ void mbar_wait(uint32_t a, uint32_t par) {
    uint32_t done;
    asm volatile("{\n\t.reg .pred p;\n\t"
                 "mbarrier.try_wait.parity.acquire.cta.shared::cta.b64 p, [%1], %2;\n\t"
                 "selp.b32 %0,1,0,p;\n\t}" : "=r"(done) : "r"(a), "r"(par) : "memory");
    if (!done) {
        asm volatile("{\n\t.reg .pred P1;\n\tW%=:\n\t"
                     "mbarrier.try_wait.parity.acquire.cta.shared::cta.b64 P1, [%0], %1, 0x989680;\n\t"
                     "@P1 bra.uni D%=;\n\tbra.uni W%=;\n\tD%=:\n\t}"
                     :: "r"(a), "r"(par) : "memory");
    }
}
// ldmatrix x4 transposed b16: 16x16 tile -> B frags for two n8 columns
__device__ __forceinline__ void ldm_x4_trans(uint32_t& q0, uint32_t& q1,
                                             uint32_t& q2, uint32_t& q3,
                                             uint32_t addr) {
    asm volatile("ldmatrix.sync.aligned.m8n8.x4.trans.shared.b16 {%0,%1,%2,%3}, [%4];"
                 : "=r"(q0), "=r"(q1), "=r"(q2), "=r"(q3) : "r"(addr));
}
__device__ __forceinline__ void mma_f16(float* d, const uint32_t* a,
                                        uint32_t b0, uint32_t b1) {
    asm volatile(
        "mma.sync.aligned.m16n8k16.row.col.f32.f16.f16.f32 "
        "{%0,%1,%2,%3}, {%4,%5,%6,%7}, {%8,%9}, {%0,%1,%2,%3};"
        : "+f"(d[0]), "+f"(d[1]), "+f"(d[2]), "+f"(d[3])
        : "r"(a[0]), "r"(a[1]), "r"(a[2]), "r"(a[3]), "r"(b0), "r"(b1));
}

// ============================================================
// Kernel: factored GEMM, 2 CTAs/SM, MMA-first loop order.
//   per r:  G = T_h[64x129] @ W1_r[129x64]; D += pm[r,:] (x) G
// 8 warps = 2(m32) x 4(n16); A frags in regs; W1 via 33KB bulk (2 slots);
// single sH f16 buf, repacked one iteration ahead of its MMA.
// ============================================================
__global__ void __launch_bounds__(NTHR, 2)
k_main(const float* __restrict__ v, const float* __restrict__ a,
       const float* __restrict__ t, const float* __restrict__ W1,
       const float* __restrict__ b1, const float* __restrict__ W2,
       const float* __restrict__ b2, const float* __restrict__ W3,
       const float* __restrict__ b3, float* __restrict__ out)
{
    extern __shared__ float sm[];
    float* sPM = sm + SM_PM;
    const uint32_t base  = smem_u32(sm);
    const uint32_t stg_u = base + SM_STAGE * 4;
    const uint32_t sh_u  = base + SM_H * 4;
    const uint32_t mb[2] = { base + SM_MBAR * 4, base + SM_MBAR * 4 + 8 };

    const int tid  = threadIdx.x;
    const int wid  = tid >> 5;
    const int lane = tid & 31;
    const int cta  = blockIdx.x;

    const int r0    = cta * RPC;
    const int nrows = (r0 < NROW) ? min(RPC, NROW - r0) : 0;

    if (nrows > 0) {
        const int i0 = r0 / H1c;
        const int i1 = (r0 + nrows - 1) / H1c;

        // ---- startup staging in the stage region (dead before first bulk) ----
        float* vT = sm + SM_STAGE;               // [c*65 + b]
        float* a2 = sm + SM_STAGE + 8320;        // [sel*64 + b]
        for (int idx = tid; idx < Bq * Hc; idx += NTHR) {
            int b = idx >> 7, c = idx & 127;
            vT[c * 65 + b] = v[idx];
        }
        if (tid < 128) {
            int c = tid >> 6, b = tid & 63;
            int ii = c ? i1 : i0;
            a2[c * 64 + b] = (ii == 0) ? 1.f : __ldg(&a[b * Hc + ii - 1]);
        }
        __syncthreads();

        for (int idx = tid; idx < nrows * Bq; idx += NTHR) {
            int rloc = idx >> 6, b = idx & 63;
            int rg = r0 + rloc;
            int i  = rg / H1c;
            int j  = rg - i * H1c;
            float av = (i == i0) ? a2[b] : a2[64 + b];
            float vv = (j == 0) ? 1.f : vT[(j - 1) * 65 + b];
            sPM[idx] = av * vv;
        }
        __syncthreads();                          // vT/a2 dead

        float* sT = sm + SM_STAGE;                // overwrite staging with T_h
        for (int idx = tid; idx < Bq * H1c; idx += NTHR) {
            int b = idx / H1c;
            int c = idx - b * H1c;
            sT[b * ST_STRIDE + c] = (c == 0) ? 1.f : __ldg(&t[b * Hc + c - 1]);
        }
        if (tid == 0) { mbar_init(mb[0], 1); mbar_init(mb[1], 1); }
        __syncthreads();

        // ---- warp geometry: 8 warps = 2(m32) x 4(n16) ----
        const int wm = wid & 1;
        const int wn = wid >> 1;                  // 0..3
        const int g  = lane >> 2;
        const int tk = lane & 3;

        // loop-invariant A fragments (T_h) in registers
        uint32_t afr[8][2][4];
        float ar[2][2];
        #pragma unroll
        for (int mi = 0; mi < 2; mi++) {
            const int mrow = wm * 32 + mi * 16 + g;
            const float* rA  = sT + mrow * ST_STRIDE;
            const float* rA8 = sT + (mrow + 8) * ST_STRIDE;
            #pragma unroll
            for (int ks = 0; ks < 8; ks++) {
                const int c = ks * 16 + 2 * tk;
                afr[ks][mi][0] = packh2(rA [c],     rA [c + 1]);
                afr[ks][mi][1] = packh2(rA8[c],     rA8[c + 1]);
                afr[ks][mi][2] = packh2(rA [c + 8], rA [c + 9]);
                afr[ks][mi][3] = packh2(rA8[c + 8], rA8[c + 9]);
            }
            ar[mi][0] = rA [128];
            ar[mi][1] = rA8[128];
        }
        __syncthreads();                          // sT dead -> stage usable

        // ---- prologue: bulks for r0 (slot 0) and r0+1 (slot 1) ----
        if (tid == 0) {
            mbar_expect_tx(mb[0], R_BYTES);
            bulk_g2s(stg_u, W1 + (long long)r0 * STG_F, R_BYTES, mb[0]);
            if (nrows > 1) {
                mbar_expect_tx(mb[1], R_BYTES);
                bulk_g2s(stg_u + STG_F * 4, W1 + (long long)(r0 + 1) * STG_F,
                         R_BYTES, mb[1]);
            }
        }

        // ldmatrix x4 lane address inside sH
        const int lrow = lane & 7;
        const int sel  = lane >> 3;
        const uint32_t lm_off =
            (uint32_t)((((sel & 1) * 8 + lrow) * PH + wn * 16 + (sel >> 1) * 8) * 2);

        // repack helper: stage slot sl (f32 rows 0..127) -> sH (f16)
        auto repack = [&](int sl) {
            const float* st = sm + SM_STAGE + sl * STG_F;
            __half* dh = reinterpret_cast<__half*>(sm + SM_H);
            #pragma unroll
            for (int p = 0; p < 8; p++) {
                int idx = p * NTHR + tid;          // 0..2047
                int kk = idx >> 4, seg = idx & 15;
                float4 w = *reinterpret_cast<const float4*>(st + kk * 64 + seg * 4);
                uint2 u;
                u.x = packh2(w.x, w.y);
                u.y = packh2(w.z, w.w);
                *reinterpret_cast<uint2*>(dh + kk * PH + seg * 4) = u;
            }
        };

        int ph[2] = {0, 0};
        mbar_wait(mb[0], ph[0]); ph[0] ^= 1;       // slot0 full
        repack(0);
        __syncthreads();                           // sH(r=0) ready

        float dacc[2][2][4];
        #pragma unroll
        for (int mi = 0; mi < 2; mi++)
            #pragma unroll
            for (int nj = 0; nj < 2; nj++)
                #pragma unroll
                for (int q = 0; q < 4; q++) dacc[mi][nj][q] = 0.f;

        for (int r = 0; r < nrows; r++) {
            const int sl = r & 1;

            // ---- MMA(r): sH (repacked last iter) + rank-1 from stage[sl] ----
            float gacc[2][2][4];
            #pragma unroll
            for (int mi = 0; mi < 2; mi++)
                #pragma unroll
                for (int nj = 0; nj < 2; nj++)
                    #pragma unroll
                    for (int q = 0; q < 4; q++) gacc[mi][nj][q] = 0.f;

            #pragma unroll
            for (int ks = 0; ks < 8; ks++) {
                uint32_t q0, q1, q2, q3;
                ldm_x4_trans(q0, q1, q2, q3, sh_u + lm_off + ks * (16 * PH * 2));
                mma_f16(gacc[0][0], afr[ks][0], q0, q1);
                mma_f16(gacc[1][0], afr[ks][1], q0, q1);
                mma_f16(gacc[0][1], afr[ks][0], q2, q3);
                mma_f16(gacc[1][1], afr[ks][1], q2, q3);
            }
            {   // fp32 rank-1 for k = 128 (raw f32 from stage[sl])
                const float* st = sm + SM_STAGE + sl * STG_F + 128 * 64;
                #pragma unroll
                for (int nj = 0; nj < 2; nj++) {
                    float2 w0 = *reinterpret_cast<const float2*>(
                        st + wn * 16 + nj * 8 + 2 * tk);
                    #pragma unroll
                    for (int mi = 0; mi < 2; mi++) {
                        gacc[mi][nj][0] += ar[mi][0] * w0.x;
                        gacc[mi][nj][1] += ar[mi][0] * w0.y;
                        gacc[mi][nj][2] += ar[mi][1] * w0.x;
                        gacc[mi][nj][3] += ar[mi][1] * w0.y;
                    }
                }
            }
            {   // epilogue: D += pm[r,row] * G
                const float* pmr = sPM + r * Bq;
                #pragma unroll
                for (int mi = 0; mi < 2; mi++) {
                    const int mrow = wm * 32 + mi * 16 + g;
                    float p0 = pmr[mrow];
                    float p1 = pmr[mrow + 8];
                    #pragma unroll
                    for (int nj = 0; nj < 2; nj++) {
                        dacc[mi][nj][0] += p0 * gacc[mi][nj][0];
                        dacc[mi][nj][1] += p0 * gacc[mi][nj][1];
                        dacc[mi][nj][2] += p1 * gacc[mi][nj][2];
                        dacc[mi][nj][3] += p1 * gacc[mi][nj][3];
                    }
                }
            }

            __syncthreads();     // all warps done with sH and stage[sl]
            if (tid == 0 && r + 2 < nrows) {       // refill stage[sl] with r+2
                mbar_expect_tx(mb[sl], R_BYTES);
                bulk_g2s(stg_u + sl * (STG_F * 4),
                         W1 + (long long)(r0 + r + 2) * STG_F, R_BYTES, mb[sl]);
            }
            if (r + 1 < nrows) { // prepare sH for MMA(r+1)
                mbar_wait(mb[sl ^ 1], ph[sl ^ 1]); ph[sl ^ 1] ^= 1;
                repack(sl ^ 1);
                __syncthreads();
            }
        }

        // ---- accumulate into global Y1pre via REDG ----
        #pragma unroll
        for (int mi = 0; mi < 2; mi++) {
            const int mrow = wm * 32 + mi * 16 + g;
            #pragma unroll
            for (int nj = 0; nj < 2; nj++) {
                const int n = wn * 16 + nj * 8 + 2 * tk;
                atomicAdd(&g_Y1pre[mrow * N1 + n],           dacc[mi][nj][0]);
                atomicAdd(&g_Y1pre[mrow * N1 + n + 1],       dacc[mi][nj][1]);
                atomicAdd(&g_Y1pre[(mrow + 8) * N1 + n],     dacc[mi][nj][2]);
                atomicAdd(&g_Y1pre[(mrow + 8) * N1 + n + 1], dacc[mi][nj][3]);
            }
        }
    }

    // ---- last-CTA fused reduce + tail MLP ----
    __threadfence();
    __shared__ unsigned s_last;
    if (tid == 0) s_last = (atomicAdd(&g_ctr, 1u) == (unsigned)(gridDim.x - 1));
    __syncthreads();
    if (!s_last) return;

    float* sY1 = sm;                 // [b*65 + o], 4160 floats
    float* sW2 = sm + 4160;          // 2048
    float* sW3 = sm + 6208;          // 32
    float* sB2 = sm + 6240;          // 32

    for (int i = tid; i < N1 * N2; i += NTHR) sW2[i] = __ldg(&W2[i]);
    if (tid < N2) { sW3[tid] = __ldg(&W3[tid]); sB2[tid] = __ldg(&b2[tid]); }
    for (int i = tid; i < Bq * N1; i += NTHR) {
        int b = i >> 6, o = i & 63;
        float s;
        asm volatile("ld.global.cg.f32 %0, [%1];" : "=f"(s) : "l"(g_Y1pre + i));
        sY1[b * 65 + o] = fmaxf(s + __ldg(&b1[o]), 0.f);
    }
    __syncthreads();

    {   // 4 threads per batch row; each computes 8 layer-2 units
        const int b = tid >> 2;          // 0..63
        const int q = tid & 3;           // j-quarter
        float s8[8];
        #pragma unroll
        for (int jj = 0; jj < 8; jj++) s8[jj] = sB2[q * 8 + jj];
        #pragma unroll 8
        for (int o = 0; o < N1; o++) {
            float y = sY1[b * 65 + o];
            #pragma unroll
            for (int jj = 0; jj < 8; jj++)
                s8[jj] += y * sW2[o * N2 + q * 8 + jj];
        }
        float rq = 0.f;
        #pragma unroll
        for (int jj = 0; jj < 8; jj++)
            rq += fmaxf(s8[jj], 0.f) * sW3[q * 8 + jj];
        #pragma unroll
        for (int off = 2; off; off >>= 1)
            rq += __shfl_down_sync(0xFFFFFFFFu, rq, off, 4);
        if (q == 0) out[b] = rq + __ldg(&b3[0]);
    }
    __syncthreads();

    // self-clean for graph replay
    for (int i = tid; i < Bq * N1; i += NTHR) g_Y1pre[i] = 0.f;
    if (tid == 0) g_ctr = 0u;
}

// ============================================================
// Launch: v, a, t, W1, b1, W2, b2, W3, b3 ; out float[64]
// ============================================================
extern "C" void kernel_launch(void* const* d_in, const int* in_sizes, int n_in,
                              void* d_out, int out_size)
{
    const float *v  = (const float*)d_in[0];
    const float *a  = (const float*)d_in[1];
    const float *t  = (const float*)d_in[2];
    const float *W1 = (const float*)d_in[3];
    const float *b1 = (const float*)d_in[4];
    const float *W2 = (const float*)d_in[5];
    const float *b2 = (const float*)d_in[6];
    const float *W3 = (const float*)d_in[7];
    const float *b3 = (const float*)d_in[8];
    float *out = (float*)d_out;

    cudaFuncSetAttribute(k_main, cudaFuncAttributeMaxDynamicSharedMemorySize,
                         SM_FLOATS * 4);

    k_main<<<NCTA, NTHR, SM_FLOATS * 4>>>(v, a, t, W1, b1, W2, b2, W3, b3, out);
}